// round 9
// baseline (speedup 1.0000x reference)
#include <cuda_runtime.h>
#include <math.h>

#define BATCH 8
#define FEAT 512
#define NUM 512
#define KK 32
#define NSPLIT 8
#define NBLK 256

typedef unsigned long long ull;

// 1/sqrt(512): global L2 scale is exact (512 unit-norm rows per half)
#define GSC 0.04419417382415922f

// ---------------- device scratch (static, allocation-free) ----------------
__device__ float g_a[BATCH * NUM * KK];               // a[b][n][k]
__device__ float g_axp[NSPLIT * BATCH * FEAT * KK];   // partial ax  [s][b][f][k]
__device__ float g_ax2p[NSPLIT * BATCH * FEAT * KK];  // partial ax2 [s][b][f][k]
__device__ float g_asumt[BATCH * KK * 16];            // asum partials [b][k][tile]
__device__ unsigned g_cnt = 0;                        // barrier counter (self-resets)
__device__ unsigned g_gen = 0;                        // barrier generation (monotonic)

__device__ __forceinline__ float wsum(float v) {
#pragma unroll
    for (int o = 16; o; o >>= 1) v += __shfl_xor_sync(0xffffffffu, v, o);
    return v;
}
__device__ __forceinline__ float wmax(float v) {
#pragma unroll
    for (int o = 16; o; o >>= 1) v = fmaxf(v, __shfl_xor_sync(0xffffffffu, v, o));
    return v;
}

// packed f32x2 helpers (sm_100+)
__device__ __forceinline__ ull pk(float lo, float hi) {
    ull r;
    asm("mov.b64 %0, {%1, %2};" : "=l"(r) : "f"(lo), "f"(hi));
    return r;
}
__device__ __forceinline__ void upk(float& lo, float& hi, ull v) {
    asm("mov.b64 {%0, %1}, %2;" : "=f"(lo), "=f"(hi) : "l"(v));
}
__device__ __forceinline__ void ffma2(ull& d, ull a, ull b) {
    asm("fma.rn.f32x2 %0, %1, %2, %0;" : "+l"(d) : "l"(a), "l"(b));
}
__device__ __forceinline__ ull fmul2(ull a, ull b) {
    ull r;
    asm("mul.rn.f32x2 %0, %1, %2;" : "=l"(r) : "l"(a), "l"(b));
    return r;
}

// Replay-safe grid barrier (volatile-load polling, monotonic generation).
__device__ __forceinline__ void gridbar() {
    __threadfence();
    __syncthreads();
    if (threadIdx.x == 0) {
        unsigned gen = *((volatile unsigned*)&g_gen);
        if (atomicAdd(&g_cnt, 1u) == NBLK - 1u) {
            *((volatile unsigned*)&g_cnt) = 0u;
            __threadfence();
            atomicAdd(&g_gen, 1u);
        } else {
            while (*((volatile unsigned*)&g_gen) == gen) __nanosleep(64);
        }
        __threadfence();
    }
    __syncthreads();
}

// shared-memory phase union: exactly 48KB
struct P1 {
    ull   W2[KK][65];      // W dup'd; odd 8B stride -> conflict-free LDS64
    float X_s[64][32];     // [f_local][n_local]; LDS128 warp-broadcast
    float red[8][KK];
};
struct P2 {
    float A_s[128][32];    // FULL n-range a tile [n][k]; LDS128 broadcast  (16KB)
    float Xs[64 * 128];    // x tile, XOR-swizzled: Xs[f*128 + (n ^ (f&31))] (32KB)
};
union SMU {
    P1 p1;
    P2 p2;
};

// ---------------- single kernel: softmax -> bar -> gemm -> bar -> fv ---------
__global__ __launch_bounds__(256, 2) void k_all(const float* __restrict__ x,
                                                const float* __restrict__ W,
                                                const float* __restrict__ bias,
                                                const float* __restrict__ mu,
                                                const float* __restrict__ sigma,
                                                float* __restrict__ out) {
    __shared__ __align__(16) SMU sm;
    const int tid  = threadIdx.x;
    const int w    = tid >> 5;
    const int lane = tid & 31;
    const int bx   = blockIdx.x;

    // phase-2 coords
    const int ft2 = bx & 7;
    const int ns2 = (bx >> 3) & 3;
    const int b2  = bx >> 5;
    const int f02 = ft2 * 64;
    const int nb2 = ns2 * 128;

    // ================= PHASE 1: logits + softmax + asum partials =============
    // 128 CTAs: b = bx>>4, 32-n tile = bx&15. Warp owns 4 n's (2 f32x2 chains).
    if (bx < 128) {
        const int b    = bx >> 4;
        const int tile = bx & 15;
        const int n0   = tile * 32;

        ull acc01 = 0ULL, acc23 = 0ULL;

        float wr[8], xr[8];
#pragma unroll
        for (int i = 0; i < 8; i++) {
            int idx = tid + i * 256;
            wr[i] = W[(idx >> 6) * FEAT + (idx & 63)];
            xr[i] = x[((size_t)b * FEAT + (idx >> 5)) * NUM + n0 + (idx & 31)];
        }

        for (int t = 0; t < 8; t++) {
            __syncthreads();
#pragma unroll
            for (int i = 0; i < 8; i++) {
                int idx = tid + i * 256;
                sm.p1.W2[idx >> 6][idx & 63] = pk(wr[i], wr[i]);
                sm.p1.X_s[idx >> 5][idx & 31] = xr[i];
            }
            __syncthreads();
            if (t < 7) {
                const int fb = (t + 1) * 64;
#pragma unroll
                for (int i = 0; i < 8; i++) {
                    int idx = tid + i * 256;
                    wr[i] = W[(idx >> 6) * FEAT + fb + (idx & 63)];
                    xr[i] = x[((size_t)b * FEAT + fb + (idx >> 5)) * NUM + n0 + (idx & 31)];
                }
            }
#pragma unroll 8
            for (int fl = 0; fl < 64; fl++) {
                ull wvv = sm.p1.W2[lane][fl];                                             // LDS64 cf
                ulonglong2 xp = *reinterpret_cast<const ulonglong2*>(&sm.p1.X_s[fl][w * 4]); // LDS128 bc
                ffma2(acc01, wvv, xp.x);
                ffma2(acc23, wvv, xp.y);
            }
        }

        float l[4];
        upk(l[0], l[1], acc01);
        upk(l[2], l[3], acc23);

        const float bv = bias[lane];
        float pa = 0.f;
#pragma unroll
        for (int j = 0; j < 4; j++) {
            float lg = l[j] + bv;
            float m = wmax(lg);
            float e = __expf(lg - m);
            float s = wsum(e);
            float a = e / s;
            int   n = n0 + w * 4 + j;
            g_a[((size_t)b * NUM + n) * KK + lane] = a;
            pa += a;
        }
        sm.p1.red[w][lane] = pa;
        __syncthreads();
        if (tid < 32) {
            float s = 0.f;
#pragma unroll
            for (int g = 0; g < 8; g++) s += sm.p1.red[g][tid];
            g_asumt[((size_t)b * KK + tid) * 16 + tile] = s;
        }
        __syncthreads();   // p1 smem fully read before Xs overwrite (union)
    }

    // stage full X tile [64 f][128 n] pre-barrier (input-only dependency).
    // XOR-swizzled scalar stores: per warp same row, lanes consecutive n ->
    // conflict-free. Gmem reads coalesced 128B per warp.
    {
        const int sr = w * 8;   // 8 rows per warp
#pragma unroll
        for (int r = 0; r < 8; r++) {
            const int fr = sr + r;
            const int sw = fr & 31;
            const float* src = &x[((size_t)b2 * FEAT + f02 + fr) * NUM + nb2];
            float* dst = &sm.p2.Xs[fr * 128];
#pragma unroll
            for (int c = 0; c < 4; c++) {
                int nc = c * 32 + lane;
                dst[nc ^ sw] = src[nc];
            }
        }
    }

    gridbar();

    // ================= PHASE 2: ax / ax2 GEMM partials ========================
    // warp = 4k-group (kg = w&3) x n-half (nh = w>>2). thread = 2 f x 8 k.
    {
        const int kg = w & 3;
        const int nh = w >> 2;
        const int kbase = kg * 8;
        const int split = ns2 * 2 + nh;     // 8 deterministic partial buffers

        // stage FULL A tile [128 n][32 k]
#pragma unroll
        for (int i = 0; i < 4; i++) {
            int idx = tid + i * 256;
            int nl = idx >> 3, kq = (idx & 7) * 4;
            float4 v = *reinterpret_cast<const float4*>(
                &g_a[((size_t)b2 * NUM + nb2 + nl) * KK + kq]);
            *reinterpret_cast<float4*>(&sm.p2.A_s[nl][kq]) = v;
        }
        __syncthreads();

        ull a1a[4] = {0, 0, 0, 0}, a2a[4] = {0, 0, 0, 0};   // f = f02+lane
        ull a1b[4] = {0, 0, 0, 0}, a2b[4] = {0, 0, 0, 0};   // f = f02+lane+32

        const float* xrowA = &sm.p2.Xs[lane * 128];
        const float* xrowB = &sm.p2.Xs[(lane + 32) * 128];
        const int nbase = nh * 64;

#pragma unroll 4
        for (int nl = 0; nl < 64; nl++) {
            const int nsw = (nbase + nl) ^ lane;    // FIX: include n-half offset in swizzled index
            float xa = xrowA[nsw];                  // LDS32 conflict-free
            float xb = xrowB[nsw];                  // LDS32 conflict-free
            ull xaa = pk(xa, xa);
            ull xbb = pk(xb, xb);
            ull xa2 = fmul2(xaa, xaa);
            ull xb2 = fmul2(xbb, xbb);
            const float* arow = &sm.p2.A_s[nbase + nl][kbase];
            ulonglong2 a01 = *reinterpret_cast<const ulonglong2*>(arow);      // LDS128 bc
            ulonglong2 a23 = *reinterpret_cast<const ulonglong2*>(arow + 4);  // LDS128 bc
            ffma2(a1a[0], a01.x, xaa);  ffma2(a2a[0], a01.x, xa2);
            ffma2(a1a[1], a01.y, xaa);  ffma2(a2a[1], a01.y, xa2);
            ffma2(a1a[2], a23.x, xaa);  ffma2(a2a[2], a23.x, xa2);
            ffma2(a1a[3], a23.y, xaa);  ffma2(a2a[3], a23.y, xa2);
            ffma2(a1b[0], a01.x, xbb);  ffma2(a2b[0], a01.x, xb2);
            ffma2(a1b[1], a01.y, xbb);  ffma2(a2b[1], a01.y, xb2);
            ffma2(a1b[2], a23.x, xbb);  ffma2(a2b[2], a23.x, xb2);
            ffma2(a1b[3], a23.y, xbb);  ffma2(a2b[3], a23.y, xb2);
        }

        const size_t baseA = (((size_t)split * BATCH + b2) * FEAT + f02 + lane) * KK + kbase;
        const size_t baseB = baseA + (size_t)32 * KK;
        *reinterpret_cast<ulonglong2*>(&g_axp[baseA])      = make_ulonglong2(a1a[0], a1a[1]);
        *reinterpret_cast<ulonglong2*>(&g_axp[baseA + 4])  = make_ulonglong2(a1a[2], a1a[3]);
        *reinterpret_cast<ulonglong2*>(&g_ax2p[baseA])     = make_ulonglong2(a2a[0], a2a[1]);
        *reinterpret_cast<ulonglong2*>(&g_ax2p[baseA + 4]) = make_ulonglong2(a2a[2], a2a[3]);
        *reinterpret_cast<ulonglong2*>(&g_axp[baseB])      = make_ulonglong2(a1b[0], a1b[1]);
        *reinterpret_cast<ulonglong2*>(&g_axp[baseB + 4])  = make_ulonglong2(a1b[2], a1b[3]);
        *reinterpret_cast<ulonglong2*>(&g_ax2p[baseB])     = make_ulonglong2(a2b[0], a2b[1]);
        *reinterpret_cast<ulonglong2*>(&g_ax2p[baseB + 4]) = make_ulonglong2(a2b[2], a2b[3]);
    }

    gridbar();

    // ================= PHASE 3: fisher vectors + rownorm + const scale ========
    {
        const int b      = bx >> 5;
        const int fgbase = (bx & 31) * 2;

        // asum[b][k]: 16 contiguous partials -> 4x LDG.128
        float asv = 0.f;
        {
            const float4* p = reinterpret_cast<const float4*>(&g_asumt[((size_t)b * KK + lane) * 16]);
#pragma unroll
            for (int q = 0; q < 4; q++) {
                float4 v = p[q];
                asv += (v.x + v.y) + (v.z + v.w);
            }
        }

#pragma unroll
        for (int j = 0; j < 2; j++) {
            const int f = (fgbase + j) * 8 + w;
            float ax = 0.f, ax2 = 0.f;
#pragma unroll
            for (int s = 0; s < NSPLIT; s++) {
                size_t po = (((size_t)s * BATCH + b) * FEAT + f) * KK + lane;
                ax  += g_axp[po];
                ax2 += g_ax2p[po];
            }
            float muv = mu[f * KK + lane];
            float sg  = sigma[f * KK + lane];
            float fv1 = (ax - muv * asv) / sg;
            float fv2 = (ax2 - 2.f * muv * ax + muv * muv * asv) / (sg * sg) - asv;

            float n1 = sqrtf(wsum(fv1 * fv1));
            float n2 = sqrtf(wsum(fv2 * fv2));
            float v1 = fv1 / fmaxf(n1, 1e-12f) * GSC;
            float v2 = fv2 / fmaxf(n2, 1e-12f) * GSC;

            const size_t ob = (size_t)b * 2 * FEAT * KK;
            out[ob + (size_t)f * KK + lane]             = v1;
            out[ob + FEAT * KK + (size_t)f * KK + lane] = v2;
        }
    }
}

// ---------------- launch -----------------------------------------------------
extern "C" void kernel_launch(void* const* d_in, const int* in_sizes, int n_in,
                              void* d_out, int out_size) {
    (void)in_sizes; (void)n_in; (void)out_size;
    const float* x     = (const float*)d_in[0];
    const float* W     = (const float*)d_in[1];
    const float* bias  = (const float*)d_in[2];
    const float* mu    = (const float*)d_in[3];
    const float* sigma = (const float*)d_in[4];
    float* out = (float*)d_out;

    k_all<<<NBLK, 256>>>(x, W, bias, mu, sigma, out);
}

// round 10
// speedup vs baseline: 1.0503x; 1.0503x over previous
#include <cuda_runtime.h>
#include <math.h>

#define BATCH 8
#define FEAT 512
#define NUM 512
#define KK 32
#define NSPLIT 8
#define NBLK 256

typedef unsigned long long ull;

// 1/sqrt(512): global L2 scale is exact (512 unit-norm rows per half)
#define GSC 0.04419417382415922f

// ---------------- device scratch (static, allocation-free) ----------------
__device__ float g_a[BATCH * NUM * KK];               // a[b][n][k]
__device__ float g_axp[NSPLIT * BATCH * FEAT * KK];   // partial ax  [s][b][f][k]
__device__ float g_ax2p[NSPLIT * BATCH * FEAT * KK];  // partial ax2 [s][b][f][k]
__device__ float g_asumt[BATCH * KK * 32];            // asum partials [b][k][tile] (32 tiles)
__device__ unsigned g_cnt = 0;                        // barrier counter (self-resets)
__device__ unsigned g_gen = 0;                        // barrier generation (monotonic)

__device__ __forceinline__ float wsum(float v) {
#pragma unroll
    for (int o = 16; o; o >>= 1) v += __shfl_xor_sync(0xffffffffu, v, o);
    return v;
}
__device__ __forceinline__ float wmax(float v) {
#pragma unroll
    for (int o = 16; o; o >>= 1) v = fmaxf(v, __shfl_xor_sync(0xffffffffu, v, o));
    return v;
}

// packed f32x2 helpers (sm_100+)
__device__ __forceinline__ ull pk(float lo, float hi) {
    ull r;
    asm("mov.b64 %0, {%1, %2};" : "=l"(r) : "f"(lo), "f"(hi));
    return r;
}
__device__ __forceinline__ void upk(float& lo, float& hi, ull v) {
    asm("mov.b64 {%0, %1}, %2;" : "=f"(lo), "=f"(hi) : "l"(v));
}
__device__ __forceinline__ void ffma2(ull& d, ull a, ull b) {
    asm("fma.rn.f32x2 %0, %1, %2, %0;" : "+l"(d) : "l"(a), "l"(b));
}
__device__ __forceinline__ ull fmul2(ull a, ull b) {
    ull r;
    asm("mul.rn.f32x2 %0, %1, %2;" : "=l"(r) : "l"(a), "l"(b));
    return r;
}

// Replay-safe grid barrier (volatile-load polling, monotonic generation).
__device__ __forceinline__ void gridbar() {
    __threadfence();
    __syncthreads();
    if (threadIdx.x == 0) {
        unsigned gen = *((volatile unsigned*)&g_gen);
        if (atomicAdd(&g_cnt, 1u) == NBLK - 1u) {
            *((volatile unsigned*)&g_cnt) = 0u;
            __threadfence();
            atomicAdd(&g_gen, 1u);
        } else {
            while (*((volatile unsigned*)&g_gen) == gen) __nanosleep(64);
        }
        __threadfence();
    }
    __syncthreads();
}

// shared-memory phase union (max 48KB)
struct P1 {
    float X4[128 * 16];        // [f][n16], 16B-aligned rows -> LDS128 broadcast  (8KB)
    float W_s[32 * 129];       // [k][f128+pad]; lane=k stride 129 -> conflict-free (16.5KB)
    float red_f[8 * 32 * 17];  // f-partial logits [warp][lane][16n+pad]          (17KB)
    float asr[8 * 33];         // asum cross-warp                                 (1KB)
};
struct P2 {
    float A_s[128 * 32];       // FULL n-range a tile [n][k]; LDS128 broadcast  (16KB)
    float Xs[64 * 128];        // x tile, XOR-swizzled: Xs[f*128 + (n ^ (f&31))] (32KB)
};
union SMU {
    P1 p1;
    P2 p2;
};

// ---------------- single kernel: softmax -> bar -> gemm -> bar -> fv ---------
__global__ __launch_bounds__(256, 2) void k_all(const float* __restrict__ x,
                                                const float* __restrict__ W,
                                                const float* __restrict__ bias,
                                                const float* __restrict__ mu,
                                                const float* __restrict__ sigma,
                                                float* __restrict__ out) {
    __shared__ __align__(16) SMU sm;
    const int tid  = threadIdx.x;
    const int w    = tid >> 5;
    const int lane = tid & 31;
    const int bx   = blockIdx.x;

    // phase-2 coords
    const int ft2 = bx & 7;
    const int ns2 = (bx >> 3) & 3;
    const int b2  = bx >> 5;
    const int f02 = ft2 * 64;
    const int nb2 = ns2 * 128;

    // ================= PHASE 1: logits + softmax + asum partials =============
    // ALL 256 CTAs: b = bx>>5, 16-n tile = bx&31. Warps split the f-dimension
    // (warp = 16 n x 16 f per chunk, 4 chunks of 128 f). 8 independent f32x2
    // accumulator chains per warp.
    {
        const int b    = bx >> 5;
        const int tile = bx & 31;
        const int n0   = tile * 16;

        ull acc[8] = {0, 0, 0, 0, 0, 0, 0, 0};

        for (int t = 0; t < 4; t++) {
            const int fb = t * 128;
            __syncthreads();
            // stage W chunk [32 k][128 f] (coalesced; conflict-free stores)
#pragma unroll
            for (int i = 0; i < 16; i++) {
                int idx = tid + i * 256;
                int k = idx >> 7, fl = idx & 127;
                sm.p1.W_s[k * 129 + fl] = W[k * FEAT + fb + fl];
            }
            // stage X chunk [128 f][16 n] (scalar, conflict-free: 16-lane groups)
#pragma unroll
            for (int i = 0; i < 8; i++) {
                int idx = tid + i * 256;
                int fr = idx >> 4, nl = idx & 15;
                sm.p1.X4[fr * 16 + nl] = x[((size_t)b * FEAT + fb + fr) * NUM + n0 + nl];
            }
            __syncthreads();
            const int fw = w * 16;
#pragma unroll 4
            for (int fi = 0; fi < 16; fi++) {
                const int fl = fw + fi;
                float wv = sm.p1.W_s[lane * 129 + fl];           // LDS32 cf (stride 129)
                ull   wp = pk(wv, wv);
                const ulonglong2* xr = reinterpret_cast<const ulonglong2*>(&sm.p1.X4[fl * 16]);
                ulonglong2 xa = xr[0];                            // LDS128 bc
                ulonglong2 xb = xr[1];                            // LDS128 bc
                ffma2(acc[0], wp, xa.x);
                ffma2(acc[1], wp, xa.y);
                ffma2(acc[2], wp, xb.x);
                ffma2(acc[3], wp, xb.y);
                xa = xr[2];                                       // LDS128 bc
                xb = xr[3];                                       // LDS128 bc
                ffma2(acc[4], wp, xa.x);
                ffma2(acc[5], wp, xa.y);
                ffma2(acc[6], wp, xb.x);
                ffma2(acc[7], wp, xb.y);
            }
        }

        // write f-partials: red_f[w][lane][16n], lane stride 17 -> conflict-free
        __syncthreads();
        {
            float* r = &sm.p1.red_f[(w * 32 + lane) * 17];
#pragma unroll
            for (int j = 0; j < 8; j++) {
                float f0, f1;
                upk(f0, f1, acc[j]);
                r[2 * j]     = f0;
                r[2 * j + 1] = f1;
            }
        }
        __syncthreads();

        // warp p combines f-partials for n-pair p, then softmaxes its 2 n's
        {
            float l0 = 0.f, l1 = 0.f;
#pragma unroll
            for (int g = 0; g < 8; g++) {
                const float* r = &sm.p1.red_f[(g * 32 + lane) * 17 + 2 * w];
                l0 += r[0];
                l1 += r[1];
            }
            const float bv = bias[lane];
            float pa;
            {
                float lg = l0 + bv;
                float m = wmax(lg);
                float e = __expf(lg - m);
                float s = wsum(e);
                float a = e / s;
                g_a[((size_t)b * NUM + n0 + 2 * w) * KK + lane] = a;
                pa = a;
            }
            {
                float lg = l1 + bv;
                float m = wmax(lg);
                float e = __expf(lg - m);
                float s = wsum(e);
                float a = e / s;
                g_a[((size_t)b * NUM + n0 + 2 * w + 1) * KK + lane] = a;
                pa += a;
            }
            sm.p1.asr[w * 33 + lane] = pa;
        }
        __syncthreads();
        if (tid < 32) {
            float s = 0.f;
#pragma unroll
            for (int g = 0; g < 8; g++) s += sm.p1.asr[g * 33 + tid];
            g_asumt[((size_t)b * KK + tid) * 32 + tile] = s;
        }
        __syncthreads();   // p1 smem fully read before Xs overwrite (union)
    }

    // stage full X tile [64 f][128 n] pre-barrier (input-only dependency).
    {
        const int sr = w * 8;   // 8 rows per warp
#pragma unroll
        for (int r = 0; r < 8; r++) {
            const int fr = sr + r;
            const int sw = fr & 31;
            const float* src = &x[((size_t)b2 * FEAT + f02 + fr) * NUM + nb2];
            float* dst = &sm.p2.Xs[fr * 128];
#pragma unroll
            for (int c = 0; c < 4; c++) {
                int nc = c * 32 + lane;
                dst[nc ^ sw] = src[nc];
            }
        }
    }

    gridbar();

    // ================= PHASE 2: ax / ax2 GEMM partials ========================
    // warp = 4k-group (kg = w&3) x n-half (nh = w>>2). thread = 2 f x 8 k.
    {
        const int kg = w & 3;
        const int nh = w >> 2;
        const int kbase = kg * 8;
        const int split = ns2 * 2 + nh;     // 8 deterministic partial buffers

        // stage FULL A tile [128 n][32 k]
#pragma unroll
        for (int i = 0; i < 4; i++) {
            int idx = tid + i * 256;
            int nl = idx >> 3, kq = (idx & 7) * 4;
            float4 v = *reinterpret_cast<const float4*>(
                &g_a[((size_t)b2 * NUM + nb2 + nl) * KK + kq]);
            *reinterpret_cast<float4*>(&sm.p2.A_s[nl * 32 + kq]) = v;
        }
        __syncthreads();

        ull a1a[4] = {0, 0, 0, 0}, a2a[4] = {0, 0, 0, 0};   // f = f02+lane
        ull a1b[4] = {0, 0, 0, 0}, a2b[4] = {0, 0, 0, 0};   // f = f02+lane+32

        const float* xrowA = &sm.p2.Xs[lane * 128];
        const float* xrowB = &sm.p2.Xs[(lane + 32) * 128];
        const int nbase = nh * 64;

#pragma unroll 4
        for (int nl = 0; nl < 64; nl++) {
            const int nsw = (nbase + nl) ^ lane;    // swizzled n index (incl. half offset)
            float xa = xrowA[nsw];                  // LDS32 conflict-free
            float xb = xrowB[nsw];                  // LDS32 conflict-free
            ull xaa = pk(xa, xa);
            ull xbb = pk(xb, xb);
            ull xa2 = fmul2(xaa, xaa);
            ull xb2 = fmul2(xbb, xbb);
            const float* arow = &sm.p2.A_s[(nbase + nl) * 32 + kbase];
            ulonglong2 a01 = *reinterpret_cast<const ulonglong2*>(arow);      // LDS128 bc
            ulonglong2 a23 = *reinterpret_cast<const ulonglong2*>(arow + 4);  // LDS128 bc
            ffma2(a1a[0], a01.x, xaa);  ffma2(a2a[0], a01.x, xa2);
            ffma2(a1a[1], a01.y, xaa);  ffma2(a2a[1], a01.y, xa2);
            ffma2(a1a[2], a23.x, xaa);  ffma2(a2a[2], a23.x, xa2);
            ffma2(a1a[3], a23.y, xaa);  ffma2(a2a[3], a23.y, xa2);
            ffma2(a1b[0], a01.x, xbb);  ffma2(a2b[0], a01.x, xb2);
            ffma2(a1b[1], a01.y, xbb);  ffma2(a2b[1], a01.y, xb2);
            ffma2(a1b[2], a23.x, xbb);  ffma2(a2b[2], a23.x, xb2);
            ffma2(a1b[3], a23.y, xbb);  ffma2(a2b[3], a23.y, xb2);
        }

        const size_t baseA = (((size_t)split * BATCH + b2) * FEAT + f02 + lane) * KK + kbase;
        const size_t baseB = baseA + (size_t)32 * KK;
        *reinterpret_cast<ulonglong2*>(&g_axp[baseA])      = make_ulonglong2(a1a[0], a1a[1]);
        *reinterpret_cast<ulonglong2*>(&g_axp[baseA + 4])  = make_ulonglong2(a1a[2], a1a[3]);
        *reinterpret_cast<ulonglong2*>(&g_ax2p[baseA])     = make_ulonglong2(a2a[0], a2a[1]);
        *reinterpret_cast<ulonglong2*>(&g_ax2p[baseA + 4]) = make_ulonglong2(a2a[2], a2a[3]);
        *reinterpret_cast<ulonglong2*>(&g_axp[baseB])      = make_ulonglong2(a1b[0], a1b[1]);
        *reinterpret_cast<ulonglong2*>(&g_axp[baseB + 4])  = make_ulonglong2(a1b[2], a1b[3]);
        *reinterpret_cast<ulonglong2*>(&g_ax2p[baseB])     = make_ulonglong2(a2b[0], a2b[1]);
        *reinterpret_cast<ulonglong2*>(&g_ax2p[baseB + 4]) = make_ulonglong2(a2b[2], a2b[3]);
    }

    gridbar();

    // ================= PHASE 3: fisher vectors + rownorm + const scale ========
    {
        const int b      = bx >> 5;
        const int fgbase = (bx & 31) * 2;

        // asum[b][k]: 32 contiguous partials -> 8x LDG.128
        float asv = 0.f;
        {
            const float4* p = reinterpret_cast<const float4*>(&g_asumt[((size_t)b * KK + lane) * 32]);
#pragma unroll
            for (int q = 0; q < 8; q++) {
                float4 v = p[q];
                asv += (v.x + v.y) + (v.z + v.w);
            }
        }

#pragma unroll
        for (int j = 0; j < 2; j++) {
            const int f = (fgbase + j) * 8 + w;
            float ax = 0.f, ax2 = 0.f;
#pragma unroll
            for (int s = 0; s < NSPLIT; s++) {
                size_t po = (((size_t)s * BATCH + b) * FEAT + f) * KK + lane;
                ax  += g_axp[po];
                ax2 += g_ax2p[po];
            }
            float muv = mu[f * KK + lane];
            float sg  = sigma[f * KK + lane];
            float fv1 = (ax - muv * asv) / sg;
            float fv2 = (ax2 - 2.f * muv * ax + muv * muv * asv) / (sg * sg) - asv;

            float n1 = sqrtf(wsum(fv1 * fv1));
            float n2 = sqrtf(wsum(fv2 * fv2));
            float v1 = fv1 / fmaxf(n1, 1e-12f) * GSC;
            float v2 = fv2 / fmaxf(n2, 1e-12f) * GSC;

            const size_t ob = (size_t)b * 2 * FEAT * KK;
            out[ob + (size_t)f * KK + lane]             = v1;
            out[ob + FEAT * KK + (size_t)f * KK + lane] = v2;
        }
    }
}

// ---------------- launch -----------------------------------------------------
extern "C" void kernel_launch(void* const* d_in, const int* in_sizes, int n_in,
                              void* d_out, int out_size) {
    (void)in_sizes; (void)n_in; (void)out_size;
    const float* x     = (const float*)d_in[0];
    const float* W     = (const float*)d_in[1];
    const float* bias  = (const float*)d_in[2];
    const float* mu    = (const float*)d_in[3];
    const float* sigma = (const float*)d_in[4];
    float* out = (float*)d_out;

    k_all<<<NBLK, 256>>>(x, W, bias, mu, sigma, out);
}

// round 11
// speedup vs baseline: 1.0585x; 1.0078x over previous
#include <cuda_runtime.h>
#include <math.h>

#define BATCH 8
#define FEAT 512
#define NUM 512
#define KK 32
#define NSPLIT 8
#define NBLK 296      // 2 x 148 SMs: perfectly even placement, all co-resident
#define P2_UNITS 512  // phase-2 half-units: 8 n-chunks x 8 f-tiles x 8 batches

typedef unsigned long long ull;

// 1/sqrt(512): global L2 scale is exact (512 unit-norm rows per half)
#define GSC 0.04419417382415922f

// ---------------- device scratch (static, allocation-free) ----------------
__device__ float g_a[BATCH * NUM * KK];               // a[b][n][k]
__device__ float g_axp[NSPLIT * BATCH * FEAT * KK];   // partial ax  [s][b][f][k]
__device__ float g_ax2p[NSPLIT * BATCH * FEAT * KK];  // partial ax2 [s][b][f][k]
__device__ float g_asumt[BATCH * KK * 32];            // asum partials [b][k][tile]
__device__ unsigned g_cnt = 0;                        // barrier counter (self-resets)
__device__ unsigned g_gen = 0;                        // barrier generation (monotonic)
__device__ unsigned g_work = 0;                       // phase-2 dynamic unit counter

__device__ __forceinline__ float wsum(float v) {
#pragma unroll
    for (int o = 16; o; o >>= 1) v += __shfl_xor_sync(0xffffffffu, v, o);
    return v;
}
__device__ __forceinline__ float wmax(float v) {
#pragma unroll
    for (int o = 16; o; o >>= 1) v = fmaxf(v, __shfl_xor_sync(0xffffffffu, v, o));
    return v;
}

// packed f32x2 helpers (sm_100+)
__device__ __forceinline__ ull pk(float lo, float hi) {
    ull r;
    asm("mov.b64 %0, {%1, %2};" : "=l"(r) : "f"(lo), "f"(hi));
    return r;
}
__device__ __forceinline__ void upk(float& lo, float& hi, ull v) {
    asm("mov.b64 {%0, %1}, %2;" : "=f"(lo), "=f"(hi) : "l"(v));
}
__device__ __forceinline__ void ffma2(ull& d, ull a, ull b) {
    asm("fma.rn.f32x2 %0, %1, %2, %0;" : "+l"(d) : "l"(a), "l"(b));
}
__device__ __forceinline__ ull fmul2(ull a, ull b) {
    ull r;
    asm("mul.rn.f32x2 %0, %1, %2;" : "=l"(r) : "l"(a), "l"(b));
    return r;
}

// Replay-safe grid barrier. __syncthreads gives block-wide HB; tid0's gpu
// fence + release-arrive publishes the whole block (cg::grid_group pattern).
__device__ __forceinline__ void gridbar() {
    __syncthreads();
    if (threadIdx.x == 0) {
        __threadfence();
        unsigned gen = *((volatile unsigned*)&g_gen);
        if (atomicAdd(&g_cnt, 1u) == NBLK - 1u) {
            *((volatile unsigned*)&g_cnt) = 0u;
            __threadfence();
            atomicAdd(&g_gen, 1u);
        } else {
            while (*((volatile unsigned*)&g_gen) == gen) __nanosleep(64);
        }
        __threadfence();
    }
    __syncthreads();
}

// shared-memory phase union (~43.2KB; 2 CTAs/SM fit easily)
struct P1 {
    float X4[128 * 16];        // [f][n16]; 16B rows -> LDS128 broadcast     (8KB)
    float W_s[32 * 129];       // [k][128f+pad]; lane=k stride 129 cf      (16.5KB)
    float red_f[8 * 32 * 17];  // f-partial logits [warp][lane][16n+pad]    (17KB)
    float asr[8 * 33];         // asum cross-warp                            (1KB)
};
struct P2 {
    float A_s[64 * 32];        // a half-tile [n][k]; LDS128 broadcast       (8KB)
    float Xs[64 * 64];         // x half-tile, XOR-swizzled Xs[f*64+(n^(f&31))] (16KB)
};
union SMU {
    P1 p1;
    P2 p2;
};

// ---------------- single kernel: softmax -> bar -> gemm -> bar -> fv ---------
__global__ __launch_bounds__(256, 2) void k_all(const float* __restrict__ x,
                                                const float* __restrict__ W,
                                                const float* __restrict__ bias,
                                                const float* __restrict__ mu,
                                                const float* __restrict__ sigma,
                                                float* __restrict__ out) {
    __shared__ __align__(16) SMU sm;
    __shared__ int s_unit;
    const int tid  = threadIdx.x;
    const int w    = tid >> 5;
    const int lane = tid & 31;
    const int bx   = blockIdx.x;

    // reset phase-2 work counter for this replay (ordered before use by gridbar)
    if (bx == 0 && tid == 0) *((volatile unsigned*)&g_work) = 0u;

    // ================= PHASE 1: logits + softmax + asum partials =============
    // 256 of 296 CTAs: b = bx>>5, 16-n tile = bx&31. Warps split f; 8
    // independent f32x2 accumulator chains per warp.
    if (bx < 256) {
        const int b    = bx >> 5;
        const int tile = bx & 31;
        const int n0   = tile * 16;

        ull acc[8] = {0, 0, 0, 0, 0, 0, 0, 0};

        for (int t = 0; t < 4; t++) {
            const int fb = t * 128;
            __syncthreads();
            // stage W chunk [32 k][128 f] (scalar; stride-129 rows, cf stores)
#pragma unroll
            for (int i = 0; i < 16; i++) {
                int idx = tid + i * 256;
                int k = idx >> 7, fl = idx & 127;
                sm.p1.W_s[k * 129 + fl] = W[k * FEAT + fb + fl];
            }
            // stage X chunk [128 f][16 n]: float4 loads + STS.128 (cf)
#pragma unroll
            for (int i = 0; i < 2; i++) {
                int idx = tid + i * 256;
                int fr = idx >> 2, c4 = (idx & 3) * 4;
                float4 v = *reinterpret_cast<const float4*>(
                    &x[((size_t)b * FEAT + fb + fr) * NUM + n0 + c4]);
                *reinterpret_cast<float4*>(&sm.p1.X4[fr * 16 + c4]) = v;
            }
            __syncthreads();
            const int fw = w * 16;
#pragma unroll 4
            for (int fi = 0; fi < 16; fi++) {
                const int fl = fw + fi;
                float wv = sm.p1.W_s[lane * 129 + fl];           // LDS32 cf
                ull   wp = pk(wv, wv);
                const ulonglong2* xr = reinterpret_cast<const ulonglong2*>(&sm.p1.X4[fl * 16]);
                ulonglong2 xa = xr[0];                            // LDS128 bc
                ulonglong2 xb = xr[1];
                ffma2(acc[0], wp, xa.x);
                ffma2(acc[1], wp, xa.y);
                ffma2(acc[2], wp, xb.x);
                ffma2(acc[3], wp, xb.y);
                xa = xr[2];
                xb = xr[3];
                ffma2(acc[4], wp, xa.x);
                ffma2(acc[5], wp, xa.y);
                ffma2(acc[6], wp, xb.x);
                ffma2(acc[7], wp, xb.y);
            }
        }

        // f-partials: red_f[w][lane][16n], lane stride 17 -> conflict-free
        __syncthreads();
        {
            float* r = &sm.p1.red_f[(w * 32 + lane) * 17];
#pragma unroll
            for (int j = 0; j < 8; j++) {
                float f0, f1;
                upk(f0, f1, acc[j]);
                r[2 * j]     = f0;
                r[2 * j + 1] = f1;
            }
        }
        __syncthreads();

        // warp p combines f-partials for n-pair p, softmaxes its 2 n's
        {
            float l0 = 0.f, l1 = 0.f;
#pragma unroll
            for (int g = 0; g < 8; g++) {
                const float* r = &sm.p1.red_f[(g * 32 + lane) * 17 + 2 * w];
                l0 += r[0];
                l1 += r[1];
            }
            const float bv = bias[lane];
            float pa;
            {
                float lg = l0 + bv;
                float m = wmax(lg);
                float e = __expf(lg - m);
                float s = wsum(e);
                float a = e / s;
                g_a[((size_t)b * NUM + n0 + 2 * w) * KK + lane] = a;
                pa = a;
            }
            {
                float lg = l1 + bv;
                float m = wmax(lg);
                float e = __expf(lg - m);
                float s = wsum(e);
                float a = e / s;
                g_a[((size_t)b * NUM + n0 + 2 * w + 1) * KK + lane] = a;
                pa += a;
            }
            sm.p1.asr[w * 33 + lane] = pa;
        }
        __syncthreads();
        if (tid < 32) {
            float s = 0.f;
#pragma unroll
            for (int g = 0; g < 8; g++) s += sm.p1.asr[g * 33 + tid];
            g_asumt[((size_t)b * KK + tid) * 32 + tile] = s;
        }
    }

    gridbar();

    // ================= PHASE 2: ax / ax2 GEMM partials (DYNAMIC) ==============
    // 512 half-units: u -> (n-chunk c = u&7, f-tile ft = (u>>3)&7, b = u>>6).
    // warp = 4 k-groups x 2 f-halves; thread = 1 f x 8 k (8 ull accs).
    {
        const int kg = w & 3;
        const int fh = w >> 2;
        const int kbase = kg * 8;
        const int flo = fh * 32 + lane;    // f within 64-tile

        for (;;) {
            __syncthreads();               // prior unit fully consumed
            if (tid == 0) s_unit = (int)atomicAdd(&g_work, 1u);
            __syncthreads();
            const int u = s_unit;
            if (u >= P2_UNITS) break;
            const int c  = u & 7;
            const int ft = (u >> 3) & 7;
            const int b  = u >> 6;
            const int f0 = ft * 64;
            const int n0 = c * 64;

            // stage A half-tile [64 n][32 k]: 2 float4/thread
#pragma unroll
            for (int i = 0; i < 2; i++) {
                int idx = tid + i * 256;
                int nl = idx >> 3, kq = (idx & 7) * 4;
                float4 v = *reinterpret_cast<const float4*>(
                    &g_a[((size_t)b * NUM + n0 + nl) * KK + kq]);
                *reinterpret_cast<float4*>(&sm.p2.A_s[nl * 32 + kq]) = v;
            }
            // stage X half-tile [64 f][64 n], XOR-swizzled, warp-per-row stores
            {
                const int sr = w * 8;
#pragma unroll
                for (int r = 0; r < 8; r++) {
                    const int fr = sr + r;
                    const int sw = fr & 31;
                    const float* src = &x[((size_t)b * FEAT + f0 + fr) * NUM + n0];
                    float* dst = &sm.p2.Xs[fr * 64];
#pragma unroll
                    for (int cc = 0; cc < 2; cc++) {
                        int nc = cc * 32 + lane;
                        dst[nc ^ sw] = src[nc];
                    }
                }
            }
            __syncthreads();

            ull a1[4] = {0, 0, 0, 0}, a2[4] = {0, 0, 0, 0};
            const float* xrow = &sm.p2.Xs[flo * 64];
#pragma unroll 8
            for (int nl = 0; nl < 64; nl++) {
                float xv = xrow[nl ^ lane];          // LDS32 cf (swizzle key = f&31 = lane)
                ull xp = pk(xv, xv);
                ull x2 = fmul2(xp, xp);
                const float* arow = &sm.p2.A_s[nl * 32 + kbase];
                ulonglong2 a01 = *reinterpret_cast<const ulonglong2*>(arow);      // LDS128 bc
                ulonglong2 a23 = *reinterpret_cast<const ulonglong2*>(arow + 4);  // LDS128 bc
                ffma2(a1[0], a01.x, xp);  ffma2(a2[0], a01.x, x2);
                ffma2(a1[1], a01.y, xp);  ffma2(a2[1], a01.y, x2);
                ffma2(a1[2], a23.x, xp);  ffma2(a2[2], a23.x, x2);
                ffma2(a1[3], a23.y, xp);  ffma2(a2[3], a23.y, x2);
            }

            const size_t base = (((size_t)c * BATCH + b) * FEAT + f0 + flo) * KK + kbase;
            *reinterpret_cast<ulonglong2*>(&g_axp[base])      = make_ulonglong2(a1[0], a1[1]);
            *reinterpret_cast<ulonglong2*>(&g_axp[base + 4])  = make_ulonglong2(a1[2], a1[3]);
            *reinterpret_cast<ulonglong2*>(&g_ax2p[base])     = make_ulonglong2(a2[0], a2[1]);
            *reinterpret_cast<ulonglong2*>(&g_ax2p[base + 4]) = make_ulonglong2(a2[2], a2[3]);
        }
    }

    gridbar();

    // ================= PHASE 3: fisher vectors + rownorm + const scale ========
    if (bx < 256) {
        const int b      = bx >> 5;
        const int fgbase = (bx & 31) * 2;

        // asum[b][k]: 32 contiguous partials -> 8x LDG.128
        float asv = 0.f;
        {
            const float4* p = reinterpret_cast<const float4*>(&g_asumt[((size_t)b * KK + lane) * 32]);
#pragma unroll
            for (int q = 0; q < 8; q++) {
                float4 v = p[q];
                asv += (v.x + v.y) + (v.z + v.w);
            }
        }

#pragma unroll
        for (int j = 0; j < 2; j++) {
            const int f = (fgbase + j) * 8 + w;
            float ax = 0.f, ax2 = 0.f;
#pragma unroll
            for (int s = 0; s < NSPLIT; s++) {
                size_t po = (((size_t)s * BATCH + b) * FEAT + f) * KK + lane;
                ax  += g_axp[po];
                ax2 += g_ax2p[po];
            }
            float muv = mu[f * KK + lane];
            float sg  = sigma[f * KK + lane];
            float fv1 = (ax - muv * asv) / sg;
            float fv2 = (ax2 - 2.f * muv * ax + muv * muv * asv) / (sg * sg) - asv;

            float n1 = sqrtf(wsum(fv1 * fv1));
            float n2 = sqrtf(wsum(fv2 * fv2));
            float v1 = fv1 / fmaxf(n1, 1e-12f) * GSC;
            float v2 = fv2 / fmaxf(n2, 1e-12f) * GSC;

            const size_t ob = (size_t)b * 2 * FEAT * KK;
            out[ob + (size_t)f * KK + lane]             = v1;
            out[ob + FEAT * KK + (size_t)f * KK + lane] = v2;
        }
    }
}

// ---------------- launch -----------------------------------------------------
extern "C" void kernel_launch(void* const* d_in, const int* in_sizes, int n_in,
                              void* d_out, int out_size) {
    (void)in_sizes; (void)n_in; (void)out_size;
    const float* x     = (const float*)d_in[0];
    const float* W     = (const float*)d_in[1];
    const float* bias  = (const float*)d_in[2];
    const float* mu    = (const float*)d_in[3];
    const float* sigma = (const float*)d_in[4];
    float* out = (float*)d_out;

    k_all<<<NBLK, 256>>>(x, W, bias, mu, sigma, out);
}